// round 10
// baseline (speedup 1.0000x reference)
#include <cuda_runtime.h>
#include <math.h>

#define BB 64
#define SS 2048
#define HH 1024
#define SPLITS 32
#define ROWS_PER_WARP (SS / SPLITS)           // 64
#define NTASKS (BB * SPLITS)                  // 2048
#define ATTN_CTAS 296                         // 2 per SM, exactly one wave
#define WARPS_PER_CTA 8
#define NBUF 3
#define ROW_BYTES (HH * 4)                    // 4096
#define ATTN_SMEM (NBUF * WARPS_PER_CTA * ROW_BYTES)   // 98304

// ---------------- scratch (no allocations allowed) ----------------
__device__ float g_scores[BB * SS];             // raw attention scores
__device__ float g_pacc[BB * SPLITS * HH];      // partial weighted sums (8 MB)
__device__ float g_pm[BB * SPLITS];             // partial running max
__device__ float g_pl[BB * SPLITS];             // partial exp-sum
__device__ float g_attn[BB * HH];               // combined attention output
__device__ float g_fc1_part[8 * BB * HH];       // fc1 split-K partials
__device__ float g_y[BB * HH];                  // post-BN-tanh activations
__device__ float g_fc2_part[8 * BB * HH];       // fc2 split-K partials

__device__ __forceinline__ void cp16(unsigned smem, const void* g) {
    asm volatile("cp.async.cg.shared.global [%0], [%1], 16;\n"
                 :: "r"(smem), "l"(g));
}
__device__ __forceinline__ void cp_commit() {
    asm volatile("cp.async.commit_group;\n");
}
__device__ __forceinline__ void cp_wait1() {
    asm volatile("cp.async.wait_group 1;\n");
}
__device__ __forceinline__ void cp_wait0() {
    asm volatile("cp.async.wait_group 0;\n");
}

#define FMA2(d, a, b) \
    asm("fma.rn.f32x2 %0, %1, %2, %0;" : "+l"(d) : "l"(a), "l"(b))

// ================= Kernel 1: warp-task attention, cp.async pipeline =========
// 1D grid of ATTN_CTAS (2/SM). Warp w of CTA c handles task c + gridDim*w,
// giving every SM 13-14 active warps (vs 16-vs-8 with a 256-CTA 2D grid).
// Each active warp streams 64 rows of ctx[:, b, :] once through a 3-deep
// smem row pipeline (loads hold zero registers).
__global__ __launch_bounds__(256) void attn_pass(
    const float* __restrict__ ctx, const float* __restrict__ key,
    const float* __restrict__ mask)
{
    extern __shared__ float smbuf[];   // [NBUF][WARPS][HH]

    const int w    = threadIdx.x >> 5;
    const int lane = threadIdx.x & 31;
    const int task = blockIdx.x + (int)gridDim.x * w;
    if (task >= NTASKS) return;        // only __syncwarp below: safe

    const int b     = task >> 5;       // SPLITS = 32
    const int split = task & 31;
    const int s0    = split * ROWS_PER_WARP;

    const float4* key4 = (const float4*)key;

    const unsigned sm_warp =
        (unsigned)__cvta_generic_to_shared(smbuf) + (unsigned)(w * ROW_BYTES);
    const unsigned buf_stride = WARPS_PER_CTA * ROW_BYTES;

    float4 kk[8];
#pragma unroll
    for (int j = 0; j < 8; j++)
        kk[j] = key4[b * (HH / 4) + j * 32 + lane];

    float4 acc[8];
#pragma unroll
    for (int j = 0; j < 8; j++) acc[j] = make_float4(0.f, 0.f, 0.f, 0.f);
    float m = -1e30f, l = 0.f;

#define ISSUE_ROW(n, s)                                                    \
    {                                                                      \
        const float* rowg = ctx + (size_t)((s) * BB + b) * HH;             \
        const unsigned sdst = sm_warp + (n) * buf_stride;                  \
        _Pragma("unroll")                                                  \
        for (int t = 0; t < 8; t++)                                        \
            cp16(sdst + (t * 32 + lane) * 16, rowg + (t * 32 + lane) * 4); \
        cp_commit();                                                       \
    }

    ISSUE_ROW(0, s0)
    ISSUE_ROW(1, s0 + 1)

    int bufr = 0;
    for (int r = 0; r < ROWS_PER_WARP; r++) {
        // last iteration has only one pending group: wait_group 1 would be
        // a no-op there (the R7 drain bug) -> wait_group 0.
        if (r + 1 < ROWS_PER_WARP) cp_wait1(); else cp_wait0();
        __syncwarp();

        const float4* rows =
            (const float4*)(smbuf + (size_t)bufr * (buf_stride / 4) + w * HH);
        float4 rv[8];
#pragma unroll
        for (int j = 0; j < 8; j++) rv[j] = rows[j * 32 + lane];

        if (r + 2 < ROWS_PER_WARP) {
            const int nb = (bufr + 2 >= NBUF) ? bufr + 2 - NBUF : bufr + 2;
            ISSUE_ROW(nb, s0 + r + 2)
        }

        float d = 0.f;
#pragma unroll
        for (int j = 0; j < 8; j++)
            d += rv[j].x * kk[j].x + rv[j].y * kk[j].y +
                 rv[j].z * kk[j].z + rv[j].w * kk[j].w;
#pragma unroll
        for (int off = 16; off > 0; off >>= 1)
            d += __shfl_xor_sync(0xffffffffu, d, off);

        const int s = s0 + r;
        d += mask[b * SS + s];
        if (lane == 0) g_scores[b * SS + s] = d;

        if (d > m) {
            const float f = __expf(m - d);
            m = d;
            l *= f;
#pragma unroll
            for (int j = 0; j < 8; j++) {
                acc[j].x *= f; acc[j].y *= f; acc[j].z *= f; acc[j].w *= f;
            }
        }
        const float p = __expf(d - m);
        l += p;
#pragma unroll
        for (int j = 0; j < 8; j++) {
            acc[j].x += p * rv[j].x; acc[j].y += p * rv[j].y;
            acc[j].z += p * rv[j].z; acc[j].w += p * rv[j].w;
        }

        bufr = (bufr + 1 == NBUF) ? 0 : bufr + 1;
    }
#undef ISSUE_ROW

    float4* pacc4 = (float4*)g_pacc;
#pragma unroll
    for (int j = 0; j < 8; j++)
        pacc4[(size_t)(b * SPLITS + split) * (HH / 4) + j * 32 + lane] = acc[j];
    if (lane == 0) {
        g_pm[b * SPLITS + split] = m;
        g_pl[b * SPLITS + split] = l;
    }
}

// ====== Kernel 2: combine split partials -> attn | normalize At ============
// grid (B, 2), block 256. phase 0: attn combine. phase 1: At normalize.
__global__ __launch_bounds__(256) void combine_kernel(float* __restrict__ out_At)
{
    const int b = blockIdx.x;
    const int tid = threadIdx.x;

    float M = -1e30f;
#pragma unroll
    for (int i = 0; i < SPLITS; i++)
        M = fmaxf(M, g_pm[b * SPLITS + i]);
    float L = 0.f;
#pragma unroll
    for (int i = 0; i < SPLITS; i++)
        L += __expf(g_pm[b * SPLITS + i] - M) * g_pl[b * SPLITS + i];
    const float invL = 1.f / L;

    if (blockIdx.y == 0) {
        float4 a = make_float4(0.f, 0.f, 0.f, 0.f);
#pragma unroll
        for (int i = 0; i < SPLITS; i++) {
            const float f = __expf(g_pm[b * SPLITS + i] - M);
            const float4 v =
                ((const float4*)g_pacc)[(size_t)(b * SPLITS + i) * (HH / 4) + tid];
            a.x += f * v.x; a.y += f * v.y; a.z += f * v.z; a.w += f * v.w;
        }
        a.x *= invL; a.y *= invL; a.z *= invL; a.w *= invL;
        ((float4*)g_attn)[b * (HH / 4) + tid] = a;
    } else {
        const float4* sc4 = (const float4*)(g_scores + b * SS);
        float4* at4 = (float4*)(out_At + b * SS);
#pragma unroll
        for (int it = 0; it < SS / 4 / 256; it++) {
            const float4 s = sc4[it * 256 + tid];
            at4[it * 256 + tid] = make_float4(
                __expf(s.x - M) * invL, __expf(s.y - M) * invL,
                __expf(s.z - M) * invL, __expf(s.w - M) * invL);
        }
    }
}

// ============ Kernel 3/5: split-K GEMM  out[b,j] = sum_k A[b,k]*W[j,k] ======
// block 256 (16x16), tile 64b x 64j x KCHUNK. k-major smem, A duplicated so
// both fma.rn.f32x2 operands come pre-packed from shared memory.
template <int K, int KCHUNK, bool CAT>
__global__ __launch_bounds__(256) void gemm_splitk(
    const float* __restrict__ key, const float* __restrict__ W)
{
    const float* A  = CAT ? g_attn : g_y;
    float* part     = CAT ? g_fc1_part : g_fc2_part;

    const int tid = threadIdx.x;
    const int j0 = blockIdx.x * 64;
    const int k0 = blockIdx.y * KCHUNK;
    const int tx = tid & 15, ty = tid >> 4;

    __shared__ float As[32][132];   // As[k][2r] = As[k][2r+1] = A[r][k]
    __shared__ float Ws[32][68];    // Ws[k][r]  = W[j0+r][k]

    unsigned long long acc[4][2];
#pragma unroll
    for (int i = 0; i < 4; i++) { acc[i][0] = 0ull; acc[i][1] = 0ull; }

    for (int kk = 0; kk < KCHUNK; kk += 32) {
#pragma unroll
        for (int t = 0; t < 8; t++) {
            const int e = tid + t * 256;
            const int r = e >> 5, c = e & 31;
            const int kg = k0 + kk + c;
            float av;
            if (CAT)
                av = (kg < HH) ? A[r * HH + kg] : key[r * HH + kg - HH];
            else
                av = A[r * K + kg];
            *(float2*)&As[c][2 * r] = make_float2(av, av);
            Ws[c][r] = W[(size_t)(j0 + r) * K + kg];
        }
        __syncthreads();
#pragma unroll
        for (int k = 0; k < 32; k++) {
            const ulonglong2 a01 = *(const ulonglong2*)&As[k][ty * 8];
            const ulonglong2 a23 = *(const ulonglong2*)&As[k][ty * 8 + 4];
            const ulonglong2 wp  = *(const ulonglong2*)&Ws[k][tx * 4];
            FMA2(acc[0][0], a01.x, wp.x); FMA2(acc[0][1], a01.x, wp.y);
            FMA2(acc[1][0], a01.y, wp.x); FMA2(acc[1][1], a01.y, wp.y);
            FMA2(acc[2][0], a23.x, wp.x); FMA2(acc[2][1], a23.x, wp.y);
            FMA2(acc[3][0], a23.y, wp.x); FMA2(acc[3][1], a23.y, wp.y);
        }
        __syncthreads();
    }

#pragma unroll
    for (int bi = 0; bi < 4; bi++) {
        const int b = ty * 4 + bi;
        float* dst = part + (size_t)(blockIdx.y * BB + b) * HH + j0 + tx * 4;
#pragma unroll
        for (int jp = 0; jp < 2; jp++) {
            float2 v;
            v.x = __uint_as_float((unsigned)(acc[bi][jp] & 0xffffffffull));
            v.y = __uint_as_float((unsigned)(acc[bi][jp] >> 32));
            *(float2*)(dst + jp * 2) = v;
        }
    }
}

// ======== Kernel 4: reduce fc1 partials + BatchNorm(train) + tanh ==========
// grid 64, block 256: CTA = 16 features x 64 batches. 4 batches/thread-group.
// fc1_b is skipped: any per-feature constant cancels exactly in (x - mean).
__global__ __launch_bounds__(256) void bn_tanh_kernel(
    const float* __restrict__ gamma, const float* __restrict__ beta)
{
    __shared__ float sx[BB][17];      // [batch][feature-local], padded
    __shared__ float rsum[16][17];
    __shared__ float rsq[16][17];

    const int t  = threadIdx.x;
    const int jl = t & 15;
    const int bt = t >> 4;            // 0..15, each covers 4 batches
    const int j  = blockIdx.x * 16 + jl;

    float ps = 0.f, pq = 0.f;
#pragma unroll
    for (int bi = 0; bi < 4; bi++) {
        const int b = bt * 4 + bi;
        float s = 0.f;
#pragma unroll
        for (int sp = 0; sp < 8; sp++)
            s += g_fc1_part[((size_t)sp * BB + b) * HH + j];
        sx[b][jl] = s;
        ps += s;
        pq += s * s;
    }
    rsum[bt][jl] = ps;
    rsq[bt][jl]  = pq;
    __syncthreads();

    float mean = 0.f, msq = 0.f;
#pragma unroll
    for (int g = 0; g < 16; g++) {
        mean += rsum[g][jl];
        msq  += rsq[g][jl];
    }
    mean *= (1.f / BB);
    msq  *= (1.f / BB);
    const float var = msq - mean * mean;
    const float inv = rsqrtf(var + 1e-5f);
    const float gm  = gamma[j] * inv;
    const float be  = beta[j] - mean * gm;

#pragma unroll
    for (int bi = 0; bi < 4; bi++) {
        const int b = bt * 4 + bi;
        g_y[b * HH + j] = tanhf(sx[b][jl] * gm + be);
    }
}

// ======== Kernel 6: reduce fc2 partials + bias -> output x ==================
__global__ __launch_bounds__(256) void finalize_kernel(
    const float* __restrict__ fc2_b, float* __restrict__ out_x)
{
    const int i = blockIdx.x * 256 + threadIdx.x;   // 16384 float4s
    const float4* b4 = (const float4*)fc2_b;
    const float4* p4 = (const float4*)g_fc2_part;
    float4 v = b4[i & (HH / 4 - 1)];
#pragma unroll
    for (int kt = 0; kt < 8; kt++) {
        const float4 p = p4[(size_t)kt * BB * HH / 4 + i];
        v.x += p.x; v.y += p.y; v.z += p.z; v.w += p.w;
    }
    ((float4*)out_x)[i] = v;
}

// ============================ launch ========================================
extern "C" void kernel_launch(void* const* d_in, const int* in_sizes, int n_in,
                              void* d_out, int out_size)
{
    const float* ctx   = (const float*)d_in[0];
    const float* key   = (const float*)d_in[1];
    const float* mask  = (const float*)d_in[2];
    const float* fc1_w = (const float*)d_in[3];
    // d_in[4] = fc1_b (cancels in BatchNorm, unused)
    const float* bn_g  = (const float*)d_in[5];
    const float* bn_b  = (const float*)d_in[6];
    const float* fc2_w = (const float*)d_in[7];
    const float* fc2_b = (const float*)d_in[8];

    float* out_x  = (float*)d_out;              // (B, H)  = 65536 floats
    float* out_At = (float*)d_out + BB * HH;    // (B, S)  = 131072 floats

    cudaFuncSetAttribute(attn_pass,
                         cudaFuncAttributeMaxDynamicSharedMemorySize,
                         ATTN_SMEM);

    attn_pass<<<ATTN_CTAS, 256, ATTN_SMEM>>>(ctx, key, mask);
    combine_kernel<<<dim3(BB, 2), 256>>>(out_At);

    // fc1: cat([attn, key]) @ fc1_w.T   (K = 2048, 8 k-splits of 256)
    gemm_splitk<2048, 256, true><<<dim3(16, 8), 256>>>(key, fc1_w);
    bn_tanh_kernel<<<64, 256>>>(bn_g, bn_b);

    // fc2: y @ fc2_w.T                  (K = 1024, 8 k-splits of 128)
    gemm_splitk<1024, 128, false><<<dim3(16, 8), 256>>>(key, fc2_w);
    finalize_kernel<<<64, 256>>>(fc2_b, out_x);
}

// round 11
// speedup vs baseline: 1.0884x; 1.0884x over previous
#include <cuda_runtime.h>
#include <math.h>

#define BB 64
#define SS 2048
#define HH 1024
#define CTAS_PER_B 4
#define WARPS_PER_CTA 8
#define SPLITS (CTAS_PER_B * WARPS_PER_CTA)   // 32
#define ROWS_PER_WARP (SS / SPLITS)           // 64

// ---------------- scratch (no allocations allowed) ----------------
__device__ float g_scores[BB * SS];             // raw attention scores
__device__ float g_pacc[BB * SPLITS * HH];      // partial weighted sums (8 MB)
__device__ float g_pm[BB * SPLITS];             // partial running max
__device__ float g_pl[BB * SPLITS];             // partial exp-sum
__device__ float g_attn[BB * HH];               // combined attention output
__device__ float g_fc1_part[8 * BB * HH];       // fc1 split-K partials
__device__ float g_y[BB * HH];                  // post-BN-tanh activations
__device__ float g_fc2_part[8 * BB * HH];       // fc2 split-K partials

#define FMA2(d, a, b) \
    asm("fma.rn.f32x2 %0, %1, %2, %0;" : "+l"(d) : "l"(a), "l"(b))

// ================= Kernel 1: warp-per-row attention (online softmax) ========
// grid (CTAS_PER_B, B), block 256 = 8 independent warps — the R4 layout,
// which remains the fastest measured. ctx is streamed with __ldcs
// (evict-first): 512 MB read-once data should not occupy L2.
__global__ __launch_bounds__(256) void attn_pass(
    const float* __restrict__ ctx, const float* __restrict__ key,
    const float* __restrict__ mask)
{
    const int b    = blockIdx.y;
    const int w    = threadIdx.x >> 5;
    const int lane = threadIdx.x & 31;
    const int split = blockIdx.x * WARPS_PER_CTA + w;
    const int s0    = split * ROWS_PER_WARP;

    const float4* ctx4 = (const float4*)ctx;
    const float4* key4 = (const float4*)key;

    float4 kk[8];
#pragma unroll
    for (int j = 0; j < 8; j++)
        kk[j] = key4[b * (HH / 4) + j * 32 + lane];

    float4 acc[8];
#pragma unroll
    for (int j = 0; j < 8; j++) acc[j] = make_float4(0.f, 0.f, 0.f, 0.f);
    float m = -1e30f, l = 0.f;

    for (int r = 0; r < ROWS_PER_WARP; r++) {
        const int s = s0 + r;
        const float4* row = ctx4 + (size_t)(s * BB + b) * (HH / 4);
        float4 rv[8];
#pragma unroll
        for (int j = 0; j < 8; j++) rv[j] = __ldcs(&row[j * 32 + lane]);

        float d = 0.f;
#pragma unroll
        for (int j = 0; j < 8; j++)
            d += rv[j].x * kk[j].x + rv[j].y * kk[j].y +
                 rv[j].z * kk[j].z + rv[j].w * kk[j].w;
#pragma unroll
        for (int off = 16; off > 0; off >>= 1)
            d += __shfl_xor_sync(0xffffffffu, d, off);

        d += mask[b * SS + s];
        if (lane == 0) g_scores[b * SS + s] = d;

        if (d > m) {
            const float f = __expf(m - d);
            m = d;
            l *= f;
#pragma unroll
            for (int j = 0; j < 8; j++) {
                acc[j].x *= f; acc[j].y *= f; acc[j].z *= f; acc[j].w *= f;
            }
        }
        const float p = __expf(d - m);
        l += p;
#pragma unroll
        for (int j = 0; j < 8; j++) {
            acc[j].x += p * rv[j].x; acc[j].y += p * rv[j].y;
            acc[j].z += p * rv[j].z; acc[j].w += p * rv[j].w;
        }
    }

    float4* pacc4 = (float4*)g_pacc;
#pragma unroll
    for (int j = 0; j < 8; j++)
        pacc4[(size_t)(b * SPLITS + split) * (HH / 4) + j * 32 + lane] = acc[j];
    if (lane == 0) {
        g_pm[b * SPLITS + split] = m;
        g_pl[b * SPLITS + split] = l;
    }
}

// ====== Kernel 2: combine split partials -> attn | normalize At ============
// grid (B, 2), block 256. phase 0: attn combine. phase 1: At normalize.
__global__ __launch_bounds__(256) void combine_kernel(float* __restrict__ out_At)
{
    const int b = blockIdx.x;
    const int tid = threadIdx.x;

    float M = -1e30f;
#pragma unroll
    for (int i = 0; i < SPLITS; i++)
        M = fmaxf(M, g_pm[b * SPLITS + i]);
    float L = 0.f;
#pragma unroll
    for (int i = 0; i < SPLITS; i++)
        L += __expf(g_pm[b * SPLITS + i] - M) * g_pl[b * SPLITS + i];
    const float invL = 1.f / L;

    if (blockIdx.y == 0) {
        float4 a = make_float4(0.f, 0.f, 0.f, 0.f);
#pragma unroll
        for (int i = 0; i < SPLITS; i++) {
            const float f = __expf(g_pm[b * SPLITS + i] - M);
            const float4 v =
                ((const float4*)g_pacc)[(size_t)(b * SPLITS + i) * (HH / 4) + tid];
            a.x += f * v.x; a.y += f * v.y; a.z += f * v.z; a.w += f * v.w;
        }
        a.x *= invL; a.y *= invL; a.z *= invL; a.w *= invL;
        ((float4*)g_attn)[b * (HH / 4) + tid] = a;
    } else {
        const float4* sc4 = (const float4*)(g_scores + b * SS);
        float4* at4 = (float4*)(out_At + b * SS);
#pragma unroll
        for (int it = 0; it < SS / 4 / 256; it++) {
            const float4 s = sc4[it * 256 + tid];
            at4[it * 256 + tid] = make_float4(
                __expf(s.x - M) * invL, __expf(s.y - M) * invL,
                __expf(s.z - M) * invL, __expf(s.w - M) * invL);
        }
    }
}

// ============ Kernel 3/5: split-K GEMM  out[b,j] = sum_k A[b,k]*W[j,k] ======
// block 256 (16x16), tile 64b x 64j x KCHUNK. k-major smem, A duplicated so
// both fma.rn.f32x2 operands come pre-packed from shared memory.
// (f32x2 path correctness-proven in R5.)
template <int K, int KCHUNK, bool CAT>
__global__ __launch_bounds__(256) void gemm_splitk(
    const float* __restrict__ key, const float* __restrict__ W)
{
    const float* A  = CAT ? g_attn : g_y;
    float* part     = CAT ? g_fc1_part : g_fc2_part;

    const int tid = threadIdx.x;
    const int j0 = blockIdx.x * 64;
    const int k0 = blockIdx.y * KCHUNK;
    const int tx = tid & 15, ty = tid >> 4;

    __shared__ float As[32][132];   // As[k][2r] = As[k][2r+1] = A[r][k]
    __shared__ float Ws[32][68];    // Ws[k][r]  = W[j0+r][k]

    unsigned long long acc[4][2];
#pragma unroll
    for (int i = 0; i < 4; i++) { acc[i][0] = 0ull; acc[i][1] = 0ull; }

    for (int kk = 0; kk < KCHUNK; kk += 32) {
#pragma unroll
        for (int t = 0; t < 8; t++) {
            const int e = tid + t * 256;
            const int r = e >> 5, c = e & 31;
            const int kg = k0 + kk + c;
            float av;
            if (CAT)
                av = (kg < HH) ? A[r * HH + kg] : key[r * HH + kg - HH];
            else
                av = A[r * K + kg];
            *(float2*)&As[c][2 * r] = make_float2(av, av);
            Ws[c][r] = W[(size_t)(j0 + r) * K + kg];
        }
        __syncthreads();
#pragma unroll
        for (int k = 0; k < 32; k++) {
            const ulonglong2 a01 = *(const ulonglong2*)&As[k][ty * 8];
            const ulonglong2 a23 = *(const ulonglong2*)&As[k][ty * 8 + 4];
            const ulonglong2 wp  = *(const ulonglong2*)&Ws[k][tx * 4];
            FMA2(acc[0][0], a01.x, wp.x); FMA2(acc[0][1], a01.x, wp.y);
            FMA2(acc[1][0], a01.y, wp.x); FMA2(acc[1][1], a01.y, wp.y);
            FMA2(acc[2][0], a23.x, wp.x); FMA2(acc[2][1], a23.x, wp.y);
            FMA2(acc[3][0], a23.y, wp.x); FMA2(acc[3][1], a23.y, wp.y);
        }
        __syncthreads();
    }

#pragma unroll
    for (int bi = 0; bi < 4; bi++) {
        const int b = ty * 4 + bi;
        float* dst = part + (size_t)(blockIdx.y * BB + b) * HH + j0 + tx * 4;
#pragma unroll
        for (int jp = 0; jp < 2; jp++) {
            float2 v;
            v.x = __uint_as_float((unsigned)(acc[bi][jp] & 0xffffffffull));
            v.y = __uint_as_float((unsigned)(acc[bi][jp] >> 32));
            *(float2*)(dst + jp * 2) = v;
        }
    }
}

// ======== Kernel 4: reduce fc1 partials + BatchNorm(train) + tanh ==========
// grid 128, block 256: CTA = 8 features x 64 batches, 2 batches/thread-group.
// fc1_b is skipped: any per-feature constant cancels exactly in (x - mean).
__global__ __launch_bounds__(256) void bn_tanh_kernel(
    const float* __restrict__ gamma, const float* __restrict__ beta)
{
    __shared__ float rsum[32][9];
    __shared__ float rsq[32][9];

    const int t  = threadIdx.x;
    const int jl = t & 7;
    const int bt = t >> 3;            // 0..31, each covers 2 batches
    const int j  = blockIdx.x * 8 + jl;

    float xv[2];
    float ps = 0.f, pq = 0.f;
#pragma unroll
    for (int bi = 0; bi < 2; bi++) {
        const int b = bt * 2 + bi;
        float s = 0.f;
#pragma unroll
        for (int sp = 0; sp < 8; sp++)
            s += g_fc1_part[((size_t)sp * BB + b) * HH + j];
        xv[bi] = s;
        ps += s;
        pq += s * s;
    }
    rsum[bt][jl] = ps;
    rsq[bt][jl]  = pq;
    __syncthreads();

    float mean = 0.f, msq = 0.f;
#pragma unroll
    for (int g = 0; g < 32; g++) {
        mean += rsum[g][jl];
        msq  += rsq[g][jl];
    }
    mean *= (1.f / BB);
    msq  *= (1.f / BB);
    const float var = msq - mean * mean;
    const float inv = rsqrtf(var + 1e-5f);
    const float gm  = gamma[j] * inv;
    const float be  = beta[j] - mean * gm;

#pragma unroll
    for (int bi = 0; bi < 2; bi++) {
        const int b = bt * 2 + bi;
        g_y[b * HH + j] = tanhf(xv[bi] * gm + be);
    }
}

// ======== Kernel 6: reduce fc2 partials + bias -> output x ==================
__global__ __launch_bounds__(256) void finalize_kernel(
    const float* __restrict__ fc2_b, float* __restrict__ out_x)
{
    const int i = blockIdx.x * 256 + threadIdx.x;   // 16384 float4s
    const float4* b4 = (const float4*)fc2_b;
    const float4* p4 = (const float4*)g_fc2_part;
    float4 v = b4[i & (HH / 4 - 1)];
#pragma unroll
    for (int kt = 0; kt < 8; kt++) {
        const float4 p = p4[(size_t)kt * BB * HH / 4 + i];
        v.x += p.x; v.y += p.y; v.z += p.z; v.w += p.w;
    }
    ((float4*)out_x)[i] = v;
}

// ============================ launch ========================================
extern "C" void kernel_launch(void* const* d_in, const int* in_sizes, int n_in,
                              void* d_out, int out_size)
{
    const float* ctx   = (const float*)d_in[0];
    const float* key   = (const float*)d_in[1];
    const float* mask  = (const float*)d_in[2];
    const float* fc1_w = (const float*)d_in[3];
    // d_in[4] = fc1_b (cancels in BatchNorm, unused)
    const float* bn_g  = (const float*)d_in[5];
    const float* bn_b  = (const float*)d_in[6];
    const float* fc2_w = (const float*)d_in[7];
    const float* fc2_b = (const float*)d_in[8];

    float* out_x  = (float*)d_out;              // (B, H)  = 65536 floats
    float* out_At = (float*)d_out + BB * HH;    // (B, S)  = 131072 floats

    attn_pass<<<dim3(CTAS_PER_B, BB), 256>>>(ctx, key, mask);
    combine_kernel<<<dim3(BB, 2), 256>>>(out_At);

    // fc1: cat([attn, key]) @ fc1_w.T   (K = 2048, 8 k-splits of 256)
    gemm_splitk<2048, 256, true><<<dim3(16, 8), 256>>>(key, fc1_w);
    bn_tanh_kernel<<<128, 256>>>(bn_g, bn_b);

    // fc2: y @ fc2_w.T                  (K = 1024, 8 k-splits of 128)
    gemm_splitk<1024, 128, false><<<dim3(16, 8), 256>>>(key, fc2_w);
    finalize_kernel<<<64, 256>>>(fc2_b, out_x);
}

// round 12
// speedup vs baseline: 1.0995x; 1.0102x over previous
#include <cuda_runtime.h>
#include <math.h>

#define BB 64
#define SS 2048
#define HH 1024
#define SPLITS 32
#define ROWS_PER_WARP (SS / SPLITS)           // 64
#define WARPS_PER_CTA 8

// ---------------- scratch (no allocations allowed) ----------------
__device__ float g_scores[BB * SS];             // raw attention scores
__device__ float g_pacc[BB * SPLITS * HH];      // partial weighted sums (8 MB)
__device__ float g_pm[BB * SPLITS];             // partial running max
__device__ float g_pl[BB * SPLITS];             // partial exp-sum
__device__ float g_attn[BB * HH];               // combined attention output
__device__ float g_fc1_part[8 * BB * HH];       // fc1 split-K partials
__device__ float g_y[BB * HH];                  // post-BN-tanh activations
__device__ float g_fc2_part[8 * BB * HH];       // fc2 split-K partials

#define FMA2(d, a, b) \
    asm("fma.rn.f32x2 %0, %1, %2, %0;" : "+l"(d) : "l"(a), "l"(b))

// ================= Kernel 1: locality-transposed attention ==================
// grid (SPLITS, BB/8), block 256 = 8 warps. Warp w owns batch b = by*8+w and
// sweeps s in [bx*64, bx*64+64). All 8 warps of a CTA move through the SAME s
// in near-lockstep, so each step the CTA reads rows (s, b0..b0+7): one
// contiguous 32 KB block — by-construction DRAM page/sector locality
// (R4's speed came from this pattern arising accidentally; R10's flattening
// destroyed it and regressed). ctx streamed with __ldcs (read-once).
__global__ __launch_bounds__(256) void attn_pass(
    const float* __restrict__ ctx, const float* __restrict__ key,
    const float* __restrict__ mask)
{
    const int w    = threadIdx.x >> 5;
    const int lane = threadIdx.x & 31;
    const int b     = blockIdx.y * WARPS_PER_CTA + w;
    const int split = blockIdx.x;
    const int s0    = split * ROWS_PER_WARP;

    const float4* ctx4 = (const float4*)ctx;
    const float4* key4 = (const float4*)key;

    float4 kk[8];
#pragma unroll
    for (int j = 0; j < 8; j++)
        kk[j] = key4[b * (HH / 4) + j * 32 + lane];

    float4 acc[8];
#pragma unroll
    for (int j = 0; j < 8; j++) acc[j] = make_float4(0.f, 0.f, 0.f, 0.f);
    float m = -1e30f, l = 0.f;

    for (int r = 0; r < ROWS_PER_WARP; r++) {
        const int s = s0 + r;
        const float4* row = ctx4 + (size_t)(s * BB + b) * (HH / 4);
        float4 rv[8];
#pragma unroll
        for (int j = 0; j < 8; j++) rv[j] = __ldcs(&row[j * 32 + lane]);

        float d = 0.f;
#pragma unroll
        for (int j = 0; j < 8; j++)
            d += rv[j].x * kk[j].x + rv[j].y * kk[j].y +
                 rv[j].z * kk[j].z + rv[j].w * kk[j].w;
#pragma unroll
        for (int off = 16; off > 0; off >>= 1)
            d += __shfl_xor_sync(0xffffffffu, d, off);

        d += mask[b * SS + s];
        if (lane == 0) g_scores[b * SS + s] = d;

        if (d > m) {
            const float f = __expf(m - d);
            m = d;
            l *= f;
#pragma unroll
            for (int j = 0; j < 8; j++) {
                acc[j].x *= f; acc[j].y *= f; acc[j].z *= f; acc[j].w *= f;
            }
        }
        const float p = __expf(d - m);
        l += p;
#pragma unroll
        for (int j = 0; j < 8; j++) {
            acc[j].x += p * rv[j].x; acc[j].y += p * rv[j].y;
            acc[j].z += p * rv[j].z; acc[j].w += p * rv[j].w;
        }
    }

    float4* pacc4 = (float4*)g_pacc;
#pragma unroll
    for (int j = 0; j < 8; j++)
        pacc4[(size_t)(b * SPLITS + split) * (HH / 4) + j * 32 + lane] = acc[j];
    if (lane == 0) {
        g_pm[b * SPLITS + split] = m;
        g_pl[b * SPLITS + split] = l;
    }
}

// ====== Kernel 2: combine split partials -> attn | normalize At ============
// grid (B, 2), block 256. phase 0: attn combine. phase 1: At normalize.
__global__ __launch_bounds__(256) void combine_kernel(float* __restrict__ out_At)
{
    const int b = blockIdx.x;
    const int tid = threadIdx.x;

    float M = -1e30f;
#pragma unroll
    for (int i = 0; i < SPLITS; i++)
        M = fmaxf(M, g_pm[b * SPLITS + i]);
    float L = 0.f;
#pragma unroll
    for (int i = 0; i < SPLITS; i++)
        L += __expf(g_pm[b * SPLITS + i] - M) * g_pl[b * SPLITS + i];
    const float invL = 1.f / L;

    if (blockIdx.y == 0) {
        float4 a = make_float4(0.f, 0.f, 0.f, 0.f);
#pragma unroll
        for (int i = 0; i < SPLITS; i++) {
            const float f = __expf(g_pm[b * SPLITS + i] - M);
            const float4 v =
                ((const float4*)g_pacc)[(size_t)(b * SPLITS + i) * (HH / 4) + tid];
            a.x += f * v.x; a.y += f * v.y; a.z += f * v.z; a.w += f * v.w;
        }
        a.x *= invL; a.y *= invL; a.z *= invL; a.w *= invL;
        ((float4*)g_attn)[b * (HH / 4) + tid] = a;
    } else {
        const float4* sc4 = (const float4*)(g_scores + b * SS);
        float4* at4 = (float4*)(out_At + b * SS);
#pragma unroll
        for (int it = 0; it < SS / 4 / 256; it++) {
            const float4 s = sc4[it * 256 + tid];
            at4[it * 256 + tid] = make_float4(
                __expf(s.x - M) * invL, __expf(s.y - M) * invL,
                __expf(s.z - M) * invL, __expf(s.w - M) * invL);
        }
    }
}

// ============ Kernel 3/5: split-K GEMM  out[b,j] = sum_k A[b,k]*W[j,k] ======
// block 256 (16x16), tile 64b x 64j x KCHUNK. k-major smem, A duplicated so
// both fma.rn.f32x2 operands come pre-packed from shared memory.
template <int K, int KCHUNK, bool CAT>
__global__ __launch_bounds__(256) void gemm_splitk(
    const float* __restrict__ key, const float* __restrict__ W)
{
    const float* A  = CAT ? g_attn : g_y;
    float* part     = CAT ? g_fc1_part : g_fc2_part;

    const int tid = threadIdx.x;
    const int j0 = blockIdx.x * 64;
    const int k0 = blockIdx.y * KCHUNK;
    const int tx = tid & 15, ty = tid >> 4;

    __shared__ float As[32][132];   // As[k][2r] = As[k][2r+1] = A[r][k]
    __shared__ float Ws[32][68];    // Ws[k][r]  = W[j0+r][k]

    unsigned long long acc[4][2];
#pragma unroll
    for (int i = 0; i < 4; i++) { acc[i][0] = 0ull; acc[i][1] = 0ull; }

    for (int kk = 0; kk < KCHUNK; kk += 32) {
#pragma unroll
        for (int t = 0; t < 8; t++) {
            const int e = tid + t * 256;
            const int r = e >> 5, c = e & 31;
            const int kg = k0 + kk + c;
            float av;
            if (CAT)
                av = (kg < HH) ? A[r * HH + kg] : key[r * HH + kg - HH];
            else
                av = A[r * K + kg];
            *(float2*)&As[c][2 * r] = make_float2(av, av);
            Ws[c][r] = W[(size_t)(j0 + r) * K + kg];
        }
        __syncthreads();
#pragma unroll
        for (int k = 0; k < 32; k++) {
            const ulonglong2 a01 = *(const ulonglong2*)&As[k][ty * 8];
            const ulonglong2 a23 = *(const ulonglong2*)&As[k][ty * 8 + 4];
            const ulonglong2 wp  = *(const ulonglong2*)&Ws[k][tx * 4];
            FMA2(acc[0][0], a01.x, wp.x); FMA2(acc[0][1], a01.x, wp.y);
            FMA2(acc[1][0], a01.y, wp.x); FMA2(acc[1][1], a01.y, wp.y);
            FMA2(acc[2][0], a23.x, wp.x); FMA2(acc[2][1], a23.x, wp.y);
            FMA2(acc[3][0], a23.y, wp.x); FMA2(acc[3][1], a23.y, wp.y);
        }
        __syncthreads();
    }

#pragma unroll
    for (int bi = 0; bi < 4; bi++) {
        const int b = ty * 4 + bi;
        float* dst = part + (size_t)(blockIdx.y * BB + b) * HH + j0 + tx * 4;
#pragma unroll
        for (int jp = 0; jp < 2; jp++) {
            float2 v;
            v.x = __uint_as_float((unsigned)(acc[bi][jp] & 0xffffffffull));
            v.y = __uint_as_float((unsigned)(acc[bi][jp] >> 32));
            *(float2*)(dst + jp * 2) = v;
        }
    }
}

// ======== Kernel 4: reduce fc1 partials + BatchNorm(train) + tanh ==========
// grid 128, block 256: CTA = 8 features x 64 batches, 2 batches/thread-group.
// fc1_b is skipped: any per-feature constant cancels exactly in (x - mean).
__global__ __launch_bounds__(256) void bn_tanh_kernel(
    const float* __restrict__ gamma, const float* __restrict__ beta)
{
    __shared__ float rsum[32][9];
    __shared__ float rsq[32][9];

    const int t  = threadIdx.x;
    const int jl = t & 7;
    const int bt = t >> 3;            // 0..31, each covers 2 batches
    const int j  = blockIdx.x * 8 + jl;

    float xv[2];
    float ps = 0.f, pq = 0.f;
#pragma unroll
    for (int bi = 0; bi < 2; bi++) {
        const int b = bt * 2 + bi;
        float s = 0.f;
#pragma unroll
        for (int sp = 0; sp < 8; sp++)
            s += g_fc1_part[((size_t)sp * BB + b) * HH + j];
        xv[bi] = s;
        ps += s;
        pq += s * s;
    }
    rsum[bt][jl] = ps;
    rsq[bt][jl]  = pq;
    __syncthreads();

    float mean = 0.f, msq = 0.f;
#pragma unroll
    for (int g = 0; g < 32; g++) {
        mean += rsum[g][jl];
        msq  += rsq[g][jl];
    }
    mean *= (1.f / BB);
    msq  *= (1.f / BB);
    const float var = msq - mean * mean;
    const float inv = rsqrtf(var + 1e-5f);
    const float gm  = gamma[j] * inv;
    const float be  = beta[j] - mean * gm;

#pragma unroll
    for (int bi = 0; bi < 2; bi++) {
        const int b = bt * 2 + bi;
        g_y[b * HH + j] = tanhf(xv[bi] * gm + be);
    }
}

// ======== Kernel 6: reduce fc2 partials + bias -> output x ==================
__global__ __launch_bounds__(256) void finalize_kernel(
    const float* __restrict__ fc2_b, float* __restrict__ out_x)
{
    const int i = blockIdx.x * 256 + threadIdx.x;   // 16384 float4s
    const float4* b4 = (const float4*)fc2_b;
    const float4* p4 = (const float4*)g_fc2_part;
    float4 v = b4[i & (HH / 4 - 1)];
#pragma unroll
    for (int kt = 0; kt < 8; kt++) {
        const float4 p = p4[(size_t)kt * BB * HH / 4 + i];
        v.x += p.x; v.y += p.y; v.z += p.z; v.w += p.w;
    }
    ((float4*)out_x)[i] = v;
}

// ============================ launch ========================================
extern "C" void kernel_launch(void* const* d_in, const int* in_sizes, int n_in,
                              void* d_out, int out_size)
{
    const float* ctx   = (const float*)d_in[0];
    const float* key   = (const float*)d_in[1];
    const float* mask  = (const float*)d_in[2];
    const float* fc1_w = (const float*)d_in[3];
    // d_in[4] = fc1_b (cancels in BatchNorm, unused)
    const float* bn_g  = (const float*)d_in[5];
    const float* bn_b  = (const float*)d_in[6];
    const float* fc2_w = (const float*)d_in[7];
    const float* fc2_b = (const float*)d_in[8];

    float* out_x  = (float*)d_out;              // (B, H)  = 65536 floats
    float* out_At = (float*)d_out + BB * HH;    // (B, S)  = 131072 floats

    attn_pass<<<dim3(SPLITS, BB / WARPS_PER_CTA), 256>>>(ctx, key, mask);
    combine_kernel<<<dim3(BB, 2), 256>>>(out_At);

    // fc1: cat([attn, key]) @ fc1_w.T   (K = 2048, 8 k-splits of 256)
    gemm_splitk<2048, 256, true><<<dim3(16, 8), 256>>>(key, fc1_w);
    bn_tanh_kernel<<<128, 256>>>(bn_g, bn_b);

    // fc2: y @ fc2_w.T                  (K = 1024, 8 k-splits of 128)
    gemm_splitk<1024, 128, false><<<dim3(16, 8), 256>>>(key, fc2_w);
    finalize_kernel<<<64, 256>>>(fc2_b, out_x);
}

// round 13
// speedup vs baseline: 1.1223x; 1.0207x over previous
#include <cuda_runtime.h>
#include <math.h>

#define BB 64
#define SS 2048
#define HH 1024
#define SPLITS 32
#define ROWS_PER_WARP (SS / SPLITS)           // 64
#define WARPS_PER_CTA 8

// ---------------- scratch (no allocations allowed) ----------------
__device__ float g_scores[BB * SS];             // raw attention scores
__device__ float g_pacc[BB * SPLITS * HH];      // partial weighted sums (8 MB)
__device__ float g_pm[BB * SPLITS];             // partial running max
__device__ float g_pl[BB * SPLITS];             // partial exp-sum
__device__ float g_attn[BB * HH];               // combined attention output
__device__ float g_fc1_part[16 * BB * HH];      // fc1 split-K partials
__device__ float g_y[BB * HH];                  // post-BN-tanh activations
__device__ float g_fc2_part[16 * BB * HH];      // fc2 split-K partials

#define FMA2(d, a, b) \
    asm("fma.rn.f32x2 %0, %1, %2, %0;" : "+l"(d) : "l"(a), "l"(b))

// ================= Kernel 1: locality-transposed attention ==================
// grid (SPLITS, BB/8), block 256 = 8 warps. Warp w owns batch b = by*8+w and
// sweeps s in [bx*64, bx*64+64). All 8 warps of a CTA move through the SAME s
// in near-lockstep, so each step the CTA reads rows (s, b0..b0+7): one
// contiguous 32 KB block. ctx streamed with __ldcs (read-once).
// Frozen at R12 form: best of five measured attn variants.
__global__ __launch_bounds__(256) void attn_pass(
    const float* __restrict__ ctx, const float* __restrict__ key,
    const float* __restrict__ mask)
{
    const int w    = threadIdx.x >> 5;
    const int lane = threadIdx.x & 31;
    const int b     = blockIdx.y * WARPS_PER_CTA + w;
    const int split = blockIdx.x;
    const int s0    = split * ROWS_PER_WARP;

    const float4* ctx4 = (const float4*)ctx;
    const float4* key4 = (const float4*)key;

    float4 kk[8];
#pragma unroll
    for (int j = 0; j < 8; j++)
        kk[j] = key4[b * (HH / 4) + j * 32 + lane];

    float4 acc[8];
#pragma unroll
    for (int j = 0; j < 8; j++) acc[j] = make_float4(0.f, 0.f, 0.f, 0.f);
    float m = -1e30f, l = 0.f;

    for (int r = 0; r < ROWS_PER_WARP; r++) {
        const int s = s0 + r;
        const float4* row = ctx4 + (size_t)(s * BB + b) * (HH / 4);
        float4 rv[8];
#pragma unroll
        for (int j = 0; j < 8; j++) rv[j] = __ldcs(&row[j * 32 + lane]);

        float d = 0.f;
#pragma unroll
        for (int j = 0; j < 8; j++)
            d += rv[j].x * kk[j].x + rv[j].y * kk[j].y +
                 rv[j].z * kk[j].z + rv[j].w * kk[j].w;
#pragma unroll
        for (int off = 16; off > 0; off >>= 1)
            d += __shfl_xor_sync(0xffffffffu, d, off);

        d += mask[b * SS + s];
        if (lane == 0) g_scores[b * SS + s] = d;

        if (d > m) {
            const float f = __expf(m - d);
            m = d;
            l *= f;
#pragma unroll
            for (int j = 0; j < 8; j++) {
                acc[j].x *= f; acc[j].y *= f; acc[j].z *= f; acc[j].w *= f;
            }
        }
        const float p = __expf(d - m);
        l += p;
#pragma unroll
        for (int j = 0; j < 8; j++) {
            acc[j].x += p * rv[j].x; acc[j].y += p * rv[j].y;
            acc[j].z += p * rv[j].z; acc[j].w += p * rv[j].w;
        }
    }

    float4* pacc4 = (float4*)g_pacc;
#pragma unroll
    for (int j = 0; j < 8; j++)
        pacc4[(size_t)(b * SPLITS + split) * (HH / 4) + j * 32 + lane] = acc[j];
    if (lane == 0) {
        g_pm[b * SPLITS + split] = m;
        g_pl[b * SPLITS + split] = l;
    }
}

// ====== Kernel 2: combine split partials -> attn | normalize At ============
// grid (B, 2), block 256. phase 0: attn combine. phase 1: At normalize.
__global__ __launch_bounds__(256) void combine_kernel(float* __restrict__ out_At)
{
    const int b = blockIdx.x;
    const int tid = threadIdx.x;

    float M = -1e30f;
#pragma unroll
    for (int i = 0; i < SPLITS; i++)
        M = fmaxf(M, g_pm[b * SPLITS + i]);
    float L = 0.f;
#pragma unroll
    for (int i = 0; i < SPLITS; i++)
        L += __expf(g_pm[b * SPLITS + i] - M) * g_pl[b * SPLITS + i];
    const float invL = 1.f / L;

    if (blockIdx.y == 0) {
        float4 a = make_float4(0.f, 0.f, 0.f, 0.f);
#pragma unroll
        for (int i = 0; i < SPLITS; i++) {
            const float f = __expf(g_pm[b * SPLITS + i] - M);
            const float4 v =
                ((const float4*)g_pacc)[(size_t)(b * SPLITS + i) * (HH / 4) + tid];
            a.x += f * v.x; a.y += f * v.y; a.z += f * v.z; a.w += f * v.w;
        }
        a.x *= invL; a.y *= invL; a.z *= invL; a.w *= invL;
        ((float4*)g_attn)[b * (HH / 4) + tid] = a;
    } else {
        const float4* sc4 = (const float4*)(g_scores + b * SS);
        float4* at4 = (float4*)(out_At + b * SS);
#pragma unroll
        for (int it = 0; it < SS / 4 / 256; it++) {
            const float4 s = sc4[it * 256 + tid];
            at4[it * 256 + tid] = make_float4(
                __expf(s.x - M) * invL, __expf(s.y - M) * invL,
                __expf(s.z - M) * invL, __expf(s.w - M) * invL);
        }
    }
}

// ============ Kernel 3/5: split-K GEMM  out[b,j] = sum_k A[b,k]*W[j,k] ======
// block 256 (16x16), tile 64b x 64j x KCHUNK. k-major smem, A duplicated so
// both fma.rn.f32x2 operands come pre-packed from shared memory.
template <int K, int KCHUNK, bool CAT>
__global__ __launch_bounds__(256) void gemm_splitk(
    const float* __restrict__ key, const float* __restrict__ W)
{
    const float* A  = CAT ? g_attn : g_y;
    float* part     = CAT ? g_fc1_part : g_fc2_part;

    const int tid = threadIdx.x;
    const int j0 = blockIdx.x * 64;
    const int k0 = blockIdx.y * KCHUNK;
    const int tx = tid & 15, ty = tid >> 4;

    __shared__ float As[32][132];   // As[k][2r] = As[k][2r+1] = A[r][k]
    __shared__ float Ws[32][68];    // Ws[k][r]  = W[j0+r][k]

    unsigned long long acc[4][2];
#pragma unroll
    for (int i = 0; i < 4; i++) { acc[i][0] = 0ull; acc[i][1] = 0ull; }

    for (int kk = 0; kk < KCHUNK; kk += 32) {
#pragma unroll
        for (int t = 0; t < 8; t++) {
            const int e = tid + t * 256;
            const int r = e >> 5, c = e & 31;
            const int kg = k0 + kk + c;
            float av;
            if (CAT)
                av = (kg < HH) ? A[r * HH + kg] : key[r * HH + kg - HH];
            else
                av = A[r * K + kg];
            *(float2*)&As[c][2 * r] = make_float2(av, av);
            Ws[c][r] = W[(size_t)(j0 + r) * K + kg];
        }
        __syncthreads();
#pragma unroll
        for (int k = 0; k < 32; k++) {
            const ulonglong2 a01 = *(const ulonglong2*)&As[k][ty * 8];
            const ulonglong2 a23 = *(const ulonglong2*)&As[k][ty * 8 + 4];
            const ulonglong2 wp  = *(const ulonglong2*)&Ws[k][tx * 4];
            FMA2(acc[0][0], a01.x, wp.x); FMA2(acc[0][1], a01.x, wp.y);
            FMA2(acc[1][0], a01.y, wp.x); FMA2(acc[1][1], a01.y, wp.y);
            FMA2(acc[2][0], a23.x, wp.x); FMA2(acc[2][1], a23.x, wp.y);
            FMA2(acc[3][0], a23.y, wp.x); FMA2(acc[3][1], a23.y, wp.y);
        }
        __syncthreads();
    }

#pragma unroll
    for (int bi = 0; bi < 4; bi++) {
        const int b = ty * 4 + bi;
        float* dst = part + (size_t)(blockIdx.y * BB + b) * HH + j0 + tx * 4;
#pragma unroll
        for (int jp = 0; jp < 2; jp++) {
            float2 v;
            v.x = __uint_as_float((unsigned)(acc[bi][jp] & 0xffffffffull));
            v.y = __uint_as_float((unsigned)(acc[bi][jp] >> 32));
            *(float2*)(dst + jp * 2) = v;
        }
    }
}

// ======== Kernel 4: reduce fc1 partials + BatchNorm(train) + tanh ==========
// grid 128, block 256: CTA = 8 features x 64 batches, 2 batches/thread-group.
// Now reduces 16 k-split partials (independent loads, latency-hidden).
// fc1_b is skipped: any per-feature constant cancels exactly in (x - mean).
__global__ __launch_bounds__(256) void bn_tanh_kernel(
    const float* __restrict__ gamma, const float* __restrict__ beta)
{
    __shared__ float rsum[32][9];
    __shared__ float rsq[32][9];

    const int t  = threadIdx.x;
    const int jl = t & 7;
    const int bt = t >> 3;            // 0..31, each covers 2 batches
    const int j  = blockIdx.x * 8 + jl;

    float xv[2];
    float ps = 0.f, pq = 0.f;
#pragma unroll
    for (int bi = 0; bi < 2; bi++) {
        const int b = bt * 2 + bi;
        float s = 0.f;
#pragma unroll
        for (int sp = 0; sp < 16; sp++)
            s += g_fc1_part[((size_t)sp * BB + b) * HH + j];
        xv[bi] = s;
        ps += s;
        pq += s * s;
    }
    rsum[bt][jl] = ps;
    rsq[bt][jl]  = pq;
    __syncthreads();

    float mean = 0.f, msq = 0.f;
#pragma unroll
    for (int g = 0; g < 32; g++) {
        mean += rsum[g][jl];
        msq  += rsq[g][jl];
    }
    mean *= (1.f / BB);
    msq  *= (1.f / BB);
    const float var = msq - mean * mean;
    const float inv = rsqrtf(var + 1e-5f);
    const float gm  = gamma[j] * inv;
    const float be  = beta[j] - mean * gm;

#pragma unroll
    for (int bi = 0; bi < 2; bi++) {
        const int b = bt * 2 + bi;
        g_y[b * HH + j] = tanhf(xv[bi] * gm + be);
    }
}

// ======== Kernel 6: reduce fc2 partials + bias -> output x ==================
__global__ __launch_bounds__(256) void finalize_kernel(
    const float* __restrict__ fc2_b, float* __restrict__ out_x)
{
    const int i = blockIdx.x * 256 + threadIdx.x;   // 16384 float4s
    const float4* b4 = (const float4*)fc2_b;
    const float4* p4 = (const float4*)g_fc2_part;
    float4 v = b4[i & (HH / 4 - 1)];
#pragma unroll
    for (int kt = 0; kt < 16; kt++) {
        const float4 p = p4[(size_t)kt * BB * HH / 4 + i];
        v.x += p.x; v.y += p.y; v.z += p.z; v.w += p.w;
    }
    ((float4*)out_x)[i] = v;
}

// ============================ launch ========================================
extern "C" void kernel_launch(void* const* d_in, const int* in_sizes, int n_in,
                              void* d_out, int out_size)
{
    const float* ctx   = (const float*)d_in[0];
    const float* key   = (const float*)d_in[1];
    const float* mask  = (const float*)d_in[2];
    const float* fc1_w = (const float*)d_in[3];
    // d_in[4] = fc1_b (cancels in BatchNorm, unused)
    const float* bn_g  = (const float*)d_in[5];
    const float* bn_b  = (const float*)d_in[6];
    const float* fc2_w = (const float*)d_in[7];
    const float* fc2_b = (const float*)d_in[8];

    float* out_x  = (float*)d_out;              // (B, H)  = 65536 floats
    float* out_At = (float*)d_out + BB * HH;    // (B, S)  = 131072 floats

    attn_pass<<<dim3(SPLITS, BB / WARPS_PER_CTA), 256>>>(ctx, key, mask);
    combine_kernel<<<dim3(BB, 2), 256>>>(out_At);

    // fc1: cat([attn, key]) @ fc1_w.T   (K = 2048, 16 k-splits of 128)
    gemm_splitk<2048, 128, true><<<dim3(16, 16), 256>>>(key, fc1_w);
    bn_tanh_kernel<<<128, 256>>>(bn_g, bn_b);

    // fc2: y @ fc2_w.T                  (K = 1024, 16 k-splits of 64)
    gemm_splitk<1024, 64, false><<<dim3(16, 16), 256>>>(key, fc2_w);
    finalize_kernel<<<64, 256>>>(fc2_b, out_x);
}